// round 7
// baseline (speedup 1.0000x reference)
#include <cuda_runtime.h>
#include <cuda_fp16.h>
#include <cstdint>

#define NENT 100000
#define NEDGE 2000000
#define NREL 1000
#define NTILE 6250          // NENT / 16
#define PITCH2 132          // smem pitch in uint2 units (B-pair rows)
#define SCAN_CH 98          // ceil(NENT / 1024)

// fused kernel block ranges (256 threads each)
#define NB_NORM 12500       // NENT*32/256
#define NB_REL  125         // NREL*32/256
#define NB_HIST 7813        // ceil(NEDGE/256)

// ---------------------------------------------------------------------------
// Scratch
// ---------------------------------------------------------------------------
__device__ uint2    g_hh[NENT * 32];          // normalized emb, fp16 row-major
__device__ uint2    g_relh[NREL * 32];        // rel emb, fp16 row-major
__device__ unsigned g_h_frag[NENT * 64];      // normalized emb, fp16 mma-A frag
__device__ unsigned g_pre_frag[NENT * 64];    // aggregation, fp16 A frag
__device__ unsigned g_hcur_frag[NENT * 64];   // hidden, fp16 A frag
__device__ float4   g_hcur[NENT * 32];        // hidden, fp32 row-major (epilogue)
__device__ uint2    g_pay[NEDGE];             // payload {src | et<<17, norm}
__device__ int g_cnt[NENT];
__device__ int g_off[NENT];
__device__ int g_cur[NENT];

__device__ __forceinline__ unsigned packh2(float a, float b) {
    __half2 h = __floats2half2_rn(a, b);
    return *(unsigned*)&h;
}

// fp16 A-fragment (m16n8k16) store for node n, lane owning cols 4*lane..4*lane+3
__device__ __forceinline__ void frag16_store4(unsigned* buf, int n, int lane,
                                              float vx, float vy, float vz, float vw) {
    int t = n >> 4, lr = n & 15;
    int g = lr & 7, rh = lr >> 3;
    int kk2 = lane >> 2;
    int kh = (lane >> 1) & 1;
    int j = rh + 2 * kh;
    int lp0 = g * 4 + ((2 * lane) & 3);
    int lp1 = g * 4 + ((2 * lane + 1) & 3);
    size_t base = ((size_t)t * 8 + kk2) * 32;
    buf[(base + lp0) * 4 + j] = packh2(vx, vy);
    buf[(base + lp1) * 4 + j] = packh2(vz, vw);
}

// ---------------------------------------------------------------------------
// Kernel 1 (fused): norm -> g_hh + g_h_frag ; rel -> g_relh ; hist atomics.
// g_cnt is re-zeroed by k_gemm1 at the END of each call (replay invariant).
// ---------------------------------------------------------------------------
__global__ void k_fused(const float4* __restrict__ ent,
                        const float4* __restrict__ rel,
                        const int* __restrict__ dst) {
    int b = blockIdx.x, t = threadIdx.x;
    if (b < NB_NORM) {
        int gw = (b * 256 + t) >> 5;
        int lane = t & 31;
        float4 v = ent[(size_t)gw * 32 + lane];
        float s = v.x * v.x + v.y * v.y + v.z * v.z + v.w * v.w;
#pragma unroll
        for (int o = 16; o; o >>= 1) s += __shfl_xor_sync(0xffffffffu, s, o);
        float inv = 1.0f / fmaxf(sqrtf(s), 1e-12f);
        v.x *= inv; v.y *= inv; v.z *= inv; v.w *= inv;
        g_hh[(size_t)gw * 32 + lane] = make_uint2(packh2(v.x, v.y), packh2(v.z, v.w));
        frag16_store4(g_h_frag, gw, lane, v.x, v.y, v.z, v.w);
    } else if (b < NB_NORM + NB_REL) {
        int gw = ((b - NB_NORM) * 256 + t) >> 5;
        int lane = t & 31;
        if (gw < NREL) {
            float4 v = rel[(size_t)gw * 32 + lane];
            g_relh[(size_t)gw * 32 + lane] = make_uint2(packh2(v.x, v.y), packh2(v.z, v.w));
        }
    } else {
        int e = (b - NB_NORM - NB_REL) * 256 + t;
        if (e < NEDGE) atomicAdd(&g_cnt[dst[e]], 1);
    }
}

// ---------------------------------------------------------------------------
// Single-block exclusive scan: g_cnt -> g_off, g_cur
// ---------------------------------------------------------------------------
__global__ void __launch_bounds__(1024, 1) k_scan() {
    __shared__ int s[1024];
    int tid = threadIdx.x;
    int i0 = tid * SCAN_CH;
    int i1 = i0 + SCAN_CH;
    if (i1 > NENT) i1 = NENT;
    int sum = 0;
    for (int i = i0; i < i1; i++) sum += g_cnt[i];
    s[tid] = sum;
    __syncthreads();
    for (int d = 1; d < 1024; d <<= 1) {
        int x = (tid >= d) ? s[tid - d] : 0;
        __syncthreads();
        s[tid] += x;
        __syncthreads();
    }
    int run = s[tid] - sum;  // exclusive prefix of this thread's chunk
    for (int i = i0; i < i1; i++) {
        int c = g_cnt[i];
        g_off[i] = run;
        g_cur[i] = run;
        run += c;
    }
}

// ---------------------------------------------------------------------------
// Scatter: 2 edges per thread, ticketed 8B payload
// ---------------------------------------------------------------------------
__global__ void k_scatter(const float2* __restrict__ enorm2,
                          const int2* __restrict__ src2,
                          const int2* __restrict__ dst2,
                          const int2* __restrict__ et2) {
    int e2 = blockIdx.x * blockDim.x + threadIdx.x;
    if (e2 >= NEDGE / 2) return;
    int2 d = dst2[e2];
    int2 s = src2[e2];
    int2 t = et2[e2];
    float2 w = enorm2[e2];
    int p0 = atomicAdd(&g_cur[d.x], 1);
    int p1 = atomicAdd(&g_cur[d.y], 1);
    g_pay[p0] = make_uint2((unsigned)s.x | ((unsigned)t.x << 17), __float_as_uint(w.x));
    g_pay[p1] = make_uint2((unsigned)s.y | ((unsigned)t.y << 17), __float_as_uint(w.y));
}

// ---------------------------------------------------------------------------
// Aggregation: 2 nodes per warp, 16 lanes per node, uint4 gathers.
// Lane sub (0-15) owns cols 8*sub .. 8*sub+7.
// ---------------------------------------------------------------------------
__global__ void k_agg() {
    int w = (blockIdx.x * blockDim.x + threadIdx.x) >> 5;
    int lane = threadIdx.x & 31;
    int node = 2 * w + (lane >> 4);
    int sub = lane & 15;
    if (node >= NENT) return;
    int cnt = g_cnt[node];
    int off = g_off[node];
    const uint4* H = (const uint4*)g_hh;
    const uint4* R = (const uint4*)g_relh;
    float acc[8];
#pragma unroll
    for (int q = 0; q < 8; q++) acc[q] = 0.f;

    int i = 0;
    for (; i + 4 <= cnt; i += 4) {
        uint2 p[4];
#pragma unroll
        for (int u = 0; u < 4; u++) p[u] = g_pay[off + i + u];
#pragma unroll
        for (int u = 0; u < 4; u++) {
            int s = p[u].x & 0x1FFFF;
            int tt = p[u].x >> 17;
            float ww = __uint_as_float(p[u].y);
            uint4 hv = H[(size_t)s * 16 + sub];
            uint4 rv = R[(size_t)tt * 16 + sub];
            float2 h0 = __half22float2(*(__half2*)&hv.x);
            float2 h1 = __half22float2(*(__half2*)&hv.y);
            float2 h2 = __half22float2(*(__half2*)&hv.z);
            float2 h3 = __half22float2(*(__half2*)&hv.w);
            float2 r0 = __half22float2(*(__half2*)&rv.x);
            float2 r1 = __half22float2(*(__half2*)&rv.y);
            float2 r2 = __half22float2(*(__half2*)&rv.z);
            float2 r3 = __half22float2(*(__half2*)&rv.w);
            acc[0] = fmaf(h0.x + r0.x, ww, acc[0]);
            acc[1] = fmaf(h0.y + r0.y, ww, acc[1]);
            acc[2] = fmaf(h1.x + r1.x, ww, acc[2]);
            acc[3] = fmaf(h1.y + r1.y, ww, acc[3]);
            acc[4] = fmaf(h2.x + r2.x, ww, acc[4]);
            acc[5] = fmaf(h2.y + r2.y, ww, acc[5]);
            acc[6] = fmaf(h3.x + r3.x, ww, acc[6]);
            acc[7] = fmaf(h3.y + r3.y, ww, acc[7]);
        }
    }
    for (; i < cnt; i++) {
        uint2 p0 = g_pay[off + i];
        int s = p0.x & 0x1FFFF;
        int tt = p0.x >> 17;
        float ww = __uint_as_float(p0.y);
        uint4 hv = H[(size_t)s * 16 + sub];
        uint4 rv = R[(size_t)tt * 16 + sub];
        float2 h0 = __half22float2(*(__half2*)&hv.x);
        float2 h1 = __half22float2(*(__half2*)&hv.y);
        float2 h2 = __half22float2(*(__half2*)&hv.z);
        float2 h3 = __half22float2(*(__half2*)&hv.w);
        float2 r0 = __half22float2(*(__half2*)&rv.x);
        float2 r1 = __half22float2(*(__half2*)&rv.y);
        float2 r2 = __half22float2(*(__half2*)&rv.z);
        float2 r3 = __half22float2(*(__half2*)&rv.w);
        acc[0] = fmaf(h0.x + r0.x, ww, acc[0]);
        acc[1] = fmaf(h0.y + r0.y, ww, acc[1]);
        acc[2] = fmaf(h1.x + r1.x, ww, acc[2]);
        acc[3] = fmaf(h1.y + r1.y, ww, acc[3]);
        acc[4] = fmaf(h2.x + r2.x, ww, acc[4]);
        acc[5] = fmaf(h2.y + r2.y, ww, acc[5]);
        acc[6] = fmaf(h3.x + r3.x, ww, acc[6]);
        acc[7] = fmaf(h3.y + r3.y, ww, acc[7]);
    }

    // frag store: cols 8*sub..8*sub+7 -> kk2 = sub>>1, kh = sub&1 fixed
    int t = node >> 4, lr = node & 15;
    int g = lr & 7, rh = lr >> 3;
    size_t base2 = ((size_t)t * 8 + (sub >> 1)) * 32;
    int j = rh + 2 * (sub & 1);
#pragma unroll
    for (int p = 0; p < 4; p++)
        g_pre_frag[(base2 + g * 4 + p) * 4 + j] = packh2(acc[2 * p], acc[2 * p + 1]);
}

// ---------------------------------------------------------------------------
// fp16 mma m16n8k16, fp32 accumulate
// ---------------------------------------------------------------------------
__device__ __forceinline__ void mma_f16(float c[4], uint4 a, unsigned b0, unsigned b1) {
    asm volatile(
        "mma.sync.aligned.m16n8k16.row.col.f32.f16.f16.f32 "
        "{%0,%1,%2,%3}, {%4,%5,%6,%7}, {%8,%9}, {%0,%1,%2,%3};"
        : "+f"(c[0]), "+f"(c[1]), "+f"(c[2]), "+f"(c[3])
        : "r"(a.x), "r"(a.y), "r"(a.z), "r"(a.w), "r"(b0), "r"(b1));
}

// ---------------------------------------------------------------------------
// GEMM1: h_cur = rrelu( [pre|h] @ [Wn;Ws] ), fp16 mma. Also re-zeroes g_cnt.
// B smem: uint2 pairs, sW2[(kk2*4+tig)*PITCH2 + c] = {b0(rows 16kk2+2tig,+1),
//                                                     b1(rows 16kk2+8+2tig,+1)} at col c.
// ---------------------------------------------------------------------------
__global__ void __launch_bounds__(512, 1)
k_gemm1(const float* __restrict__ Wn, const float* __restrict__ Ws) {
    // replay invariant: leave g_cnt zeroed for the next call's histogram
    for (int i = blockIdx.x * 512 + threadIdx.x; i < NENT; i += gridDim.x * 512)
        g_cnt[i] = 0;

    extern __shared__ uint2 sW2[];  // 64 rows x PITCH2 uint2
    for (int i = threadIdx.x; i < 64 * 128; i += blockDim.x) {
        int kq = i >> 7, c = i & 127;
        int kk2 = kq >> 2, tig = kq & 3;
        int r0 = 16 * kk2 + 2 * tig;
        int r1 = r0 + 8;
        float a0 = (r0 < 128) ? Wn[r0 * 128 + c] : Ws[(r0 - 128) * 128 + c];
        float a1 = (r0 + 1 < 128) ? Wn[(r0 + 1) * 128 + c] : Ws[(r0 - 127) * 128 + c];
        float b0 = (r1 < 128) ? Wn[r1 * 128 + c] : Ws[(r1 - 128) * 128 + c];
        float b1 = (r1 + 1 < 128) ? Wn[(r1 + 1) * 128 + c] : Ws[(r1 - 127) * 128 + c];
        sW2[kq * PITCH2 + c] = make_uint2(packh2(a0, a1), packh2(b0, b1));
    }
    __syncthreads();

    const int lane = threadIdx.x & 31;
    const int warp = threadIdx.x >> 5;
    const int g = lane >> 2, tig = lane & 3;
    const float SL = 0.22916666666666666f;
    const uint4* preF = (const uint4*)g_pre_frag;
    const uint4* hF = (const uint4*)g_h_frag;

    for (int tile = blockIdx.x * 16 + warp; tile < NTILE; tile += gridDim.x * 16) {
        int n0 = tile * 16;
        float acc[16][4];
#pragma unroll
        for (int nt = 0; nt < 16; nt++) {
            acc[nt][0] = 0.f; acc[nt][1] = 0.f; acc[nt][2] = 0.f; acc[nt][3] = 0.f;
        }

        for (int kk2 = 0; kk2 < 16; kk2++) {
            const uint4* buf = (kk2 < 8) ? preF : hF;
            int ks = kk2 & 7;
            uint4 af = buf[((size_t)tile * 8 + ks) * 32 + lane];
            const uint2* bp = sW2 + (kk2 * 4 + tig) * PITCH2 + g;
#pragma unroll
            for (int nt = 0; nt < 16; nt++) {
                uint2 bb = bp[nt * 8];
                mma_f16(acc[nt], af, bb.x, bb.y);
            }
        }

        float2* out = (float2*)g_hcur;
#pragma unroll
        for (int nt = 0; nt < 16; nt++) {
            float v0 = acc[nt][0], v1 = acc[nt][1], v2 = acc[nt][2], v3 = acc[nt][3];
            v0 = v0 >= 0.f ? v0 : SL * v0;
            v1 = v1 >= 0.f ? v1 : SL * v1;
            v2 = v2 >= 0.f ? v2 : SL * v2;
            v3 = v3 >= 0.f ? v3 : SL * v3;
            out[(size_t)(n0 + g) * 64 + nt * 4 + tig] = make_float2(v0, v1);
            out[(size_t)(n0 + 8 + g) * 64 + nt * 4 + tig] = make_float2(v2, v3);
            size_t base = ((size_t)tile * 8 + (nt >> 1)) * 32 + g * 4 + tig;
            g_hcur_frag[base * 4 + 2 * (nt & 1)]     = packh2(v0, v1);
            g_hcur_frag[base * 4 + 1 + 2 * (nt & 1)] = packh2(v2, v3);
        }
    }
}

// ---------------------------------------------------------------------------
// GEMM2 + gate: gate = sigmoid(h_cur @ Wg + b); out = gate*h_cur + (1-gate)*his
// ---------------------------------------------------------------------------
__global__ void __launch_bounds__(512, 1)
k_gemm2(const float* __restrict__ Wg, const float* __restrict__ bias,
        const float* __restrict__ his, float* __restrict__ outp) {
    extern __shared__ uint2 sW2[];  // 32 rows x PITCH2 uint2
    for (int i = threadIdx.x; i < 32 * 128; i += blockDim.x) {
        int kq = i >> 7, c = i & 127;
        int kk2 = kq >> 2, tig = kq & 3;
        int r0 = 16 * kk2 + 2 * tig;
        int r1 = r0 + 8;
        sW2[kq * PITCH2 + c] = make_uint2(
            packh2(Wg[r0 * 128 + c], Wg[(r0 + 1) * 128 + c]),
            packh2(Wg[r1 * 128 + c], Wg[(r1 + 1) * 128 + c]));
    }
    __syncthreads();

    const int lane = threadIdx.x & 31;
    const int warp = threadIdx.x >> 5;
    const int g = lane >> 2, tig = lane & 3;
    const uint4* hcF = (const uint4*)g_hcur_frag;

    float2 bs[16];
#pragma unroll
    for (int nt = 0; nt < 16; nt++)
        bs[nt] = ((const float2*)bias)[nt * 4 + tig];

    for (int tile = blockIdx.x * 16 + warp; tile < NTILE; tile += gridDim.x * 16) {
        int n0 = tile * 16;
        float acc[16][4];
#pragma unroll
        for (int nt = 0; nt < 16; nt++) {
            acc[nt][0] = 0.f; acc[nt][1] = 0.f; acc[nt][2] = 0.f; acc[nt][3] = 0.f;
        }

        for (int kk2 = 0; kk2 < 8; kk2++) {
            uint4 af = hcF[((size_t)tile * 8 + kk2) * 32 + lane];
            const uint2* bp = sW2 + (kk2 * 4 + tig) * PITCH2 + g;
#pragma unroll
            for (int nt = 0; nt < 16; nt++) {
                uint2 bb = bp[nt * 8];
                mma_f16(acc[nt], af, bb.x, bb.y);
            }
        }

        const float2* hc2 = (const float2*)g_hcur;
        const float2* hs2 = (const float2*)his;
        float2* o2 = (float2*)outp;
#pragma unroll
        for (int nt = 0; nt < 16; nt++) {
            {
                size_t idx = (size_t)(n0 + g) * 64 + nt * 4 + tig;
                float2 hc = hc2[idx];
                float2 hs = hs2[idx];
                float gx = 1.0f / (1.0f + expf(-(acc[nt][0] + bs[nt].x)));
                float gy = 1.0f / (1.0f + expf(-(acc[nt][1] + bs[nt].y)));
                float2 o;
                o.x = fmaf(gx, hc.x - hs.x, hs.x);
                o.y = fmaf(gy, hc.y - hs.y, hs.y);
                o2[idx] = o;
            }
            {
                size_t idx = (size_t)(n0 + 8 + g) * 64 + nt * 4 + tig;
                float2 hc = hc2[idx];
                float2 hs = hs2[idx];
                float gx = 1.0f / (1.0f + expf(-(acc[nt][2] + bs[nt].x)));
                float gy = 1.0f / (1.0f + expf(-(acc[nt][3] + bs[nt].y)));
                float2 o;
                o.x = fmaf(gx, hc.x - hs.x, hs.x);
                o.y = fmaf(gy, hc.y - hs.y, hs.y);
                o2[idx] = o;
            }
        }
    }
}

// ---------------------------------------------------------------------------
// Launch: 6 kernels; #4 = k_agg (profiled slot)
// ---------------------------------------------------------------------------
extern "C" void kernel_launch(void* const* d_in, const int* in_sizes, int n_in,
                              void* d_out, int out_size) {
    const float4* ent  = (const float4*)d_in[0];
    const float4* rel  = (const float4*)d_in[1];
    const float*  his  = (const float*)d_in[2];
    const float*  Wn   = (const float*)d_in[3];
    const float*  Ws   = (const float*)d_in[4];
    const float*  Wg   = (const float*)d_in[5];
    const float*  bias = (const float*)d_in[6];
    const float*  enorm = (const float*)d_in[7];
    const int*    src  = (const int*)d_in[8];
    const int*    dst  = (const int*)d_in[9];
    const int*    et   = (const int*)d_in[10];
    float* out = (float*)d_out;

    k_fused<<<NB_NORM + NB_REL + NB_HIST, 256>>>(ent, rel, dst);
    k_scan<<<1, 1024>>>();
    k_scatter<<<(NEDGE / 2 + 511) / 512, 512>>>((const float2*)enorm, (const int2*)src,
                                                (const int2*)dst, (const int2*)et);
    k_agg<<<3125, 512>>>();
    {
        int smem = 64 * PITCH2 * 8;
        cudaFuncSetAttribute(k_gemm1, cudaFuncAttributeMaxDynamicSharedMemorySize, smem);
        k_gemm1<<<148, 512, smem>>>(Wn, Ws);
    }
    {
        int smem = 32 * PITCH2 * 8;
        cudaFuncSetAttribute(k_gemm2, cudaFuncAttributeMaxDynamicSharedMemorySize, smem);
        k_gemm2<<<148, 512, smem>>>(Wg, bias, his, out);
    }
}

// round 8
// speedup vs baseline: 1.7579x; 1.7579x over previous
#include <cuda_runtime.h>
#include <cuda_fp16.h>
#include <cstdint>

#define NENT 100000
#define NEDGE 2000000
#define NREL 1000
#define NTILE 6250          // NENT / 16
#define PITCH2 132          // smem pitch in uint2 units (B-pair rows)
#define SCAN_B 196          // ceil(NENT / 512)

// fused kernel block ranges (256 threads each)
#define NB_NORM 12500       // NENT*32/256
#define NB_REL  125         // NREL*32/256
#define NB_HIST 7813        // ceil(NEDGE/256)

// ---------------------------------------------------------------------------
// Scratch
// ---------------------------------------------------------------------------
__device__ uint2    g_hh[NENT * 32];          // normalized emb, fp16 row-major
__device__ uint2    g_relh[NREL * 32];        // rel emb, fp16 row-major
__device__ unsigned g_h_frag[NENT * 64];      // normalized emb, fp16 mma-A frag
__device__ unsigned g_pre_frag[NENT * 64];    // aggregation, fp16 A frag
__device__ unsigned g_hcur_frag[NENT * 64];   // hidden, fp16 A frag
__device__ float4   g_hcur[NENT * 32];        // hidden, fp32 row-major (epilogue)
__device__ uint2    g_pay[NEDGE];             // payload {src | et<<17, norm}
__device__ int g_cnt[NENT];
__device__ int g_off[NENT];
__device__ int g_cur[NENT];
__device__ int g_part[SCAN_B];

__device__ __forceinline__ unsigned packh2(float a, float b) {
    __half2 h = __floats2half2_rn(a, b);
    return *(unsigned*)&h;
}
__device__ __forceinline__ __half2 u2h(unsigned u) { return *(__half2*)&u; }

// fp16 A-fragment (m16n8k16) store for node n, lane owning cols 4*lane..4*lane+3
__device__ __forceinline__ void frag16_store4(unsigned* buf, int n, int lane,
                                              float vx, float vy, float vz, float vw) {
    int t = n >> 4, lr = n & 15;
    int g = lr & 7, rh = lr >> 3;
    int kk2 = lane >> 2;
    int kh = (lane >> 1) & 1;
    int j = rh + 2 * kh;
    int lp0 = g * 4 + ((2 * lane) & 3);
    int lp1 = g * 4 + ((2 * lane + 1) & 3);
    size_t base = ((size_t)t * 8 + kk2) * 32;
    buf[(base + lp0) * 4 + j] = packh2(vx, vy);
    buf[(base + lp1) * 4 + j] = packh2(vz, vw);
}

// ---------------------------------------------------------------------------
// Kernel 1 (fused): norm -> g_hh + g_h_frag ; rel -> g_relh ; hist atomics.
// g_cnt is re-zeroed by k_gemm1 at the END of each call (replay invariant).
// ---------------------------------------------------------------------------
__global__ void k_fused(const float4* __restrict__ ent,
                        const float4* __restrict__ rel,
                        const int* __restrict__ dst) {
    int b = blockIdx.x, t = threadIdx.x;
    if (b < NB_NORM) {
        int gw = (b * 256 + t) >> 5;
        int lane = t & 31;
        float4 v = ent[(size_t)gw * 32 + lane];
        float s = v.x * v.x + v.y * v.y + v.z * v.z + v.w * v.w;
#pragma unroll
        for (int o = 16; o; o >>= 1) s += __shfl_xor_sync(0xffffffffu, s, o);
        float inv = 1.0f / fmaxf(sqrtf(s), 1e-12f);
        v.x *= inv; v.y *= inv; v.z *= inv; v.w *= inv;
        g_hh[(size_t)gw * 32 + lane] = make_uint2(packh2(v.x, v.y), packh2(v.z, v.w));
        frag16_store4(g_h_frag, gw, lane, v.x, v.y, v.z, v.w);
    } else if (b < NB_NORM + NB_REL) {
        int gw = ((b - NB_NORM) * 256 + t) >> 5;
        int lane = t & 31;
        if (gw < NREL) {
            float4 v = rel[(size_t)gw * 32 + lane];
            g_relh[(size_t)gw * 32 + lane] = make_uint2(packh2(v.x, v.y), packh2(v.z, v.w));
        }
    } else {
        int e = (b - NB_NORM - NB_REL) * 256 + t;
        if (e < NEDGE) atomicAdd(&g_cnt[dst[e]], 1);
    }
}

// ---------------------------------------------------------------------------
// Scan (2 kernels, R6 version — measured cheap)
// ---------------------------------------------------------------------------
__global__ void k_scan1() {
    int i = blockIdx.x * 512 + threadIdx.x;
    int v = (i < NENT) ? g_cnt[i] : 0;
    int lane = threadIdx.x & 31, wid = threadIdx.x >> 5;
#pragma unroll
    for (int o = 16; o; o >>= 1) v += __shfl_xor_sync(0xffffffffu, v, o);
    __shared__ int ws[16];
    if (lane == 0) ws[wid] = v;
    __syncthreads();
    if (threadIdx.x < 16) {
        int x = ws[threadIdx.x];
#pragma unroll
        for (int o = 8; o; o >>= 1) x += __shfl_xor_sync(0xffffu, x, o);
        if (threadIdx.x == 0) g_part[blockIdx.x] = x;
    }
}

__global__ void k_scan2() {
    __shared__ int sp[256];
    __shared__ int s[512];
    int t = threadIdx.x, b = blockIdx.x;
    if (t < 256) sp[t] = (t < SCAN_B) ? g_part[t] : 0;
    __syncthreads();
    for (int d = 1; d < 256; d <<= 1) {
        int x = 0;
        if (t < 256 && t >= d) x = sp[t - d];
        __syncthreads();
        if (t < 256) sp[t] += x;
        __syncthreads();
    }
    int base = (b == 0) ? 0 : sp[b - 1];
    int i = b * 512 + t;
    int v = (i < NENT) ? g_cnt[i] : 0;
    s[t] = v;
    __syncthreads();
    for (int d = 1; d < 512; d <<= 1) {
        int x = (t >= d) ? s[t - d] : 0;
        __syncthreads();
        s[t] += x;
        __syncthreads();
    }
    if (i < NENT) {
        int off = base + s[t] - v;
        g_off[i] = off;
        g_cur[i] = off;
    }
}

// ---------------------------------------------------------------------------
// Scatter: 1 edge per thread (R6 version — measured 31 us)
// ---------------------------------------------------------------------------
__global__ void k_scatter(const float* __restrict__ enorm,
                          const int* __restrict__ src,
                          const int* __restrict__ dst,
                          const int* __restrict__ et) {
    int e = blockIdx.x * blockDim.x + threadIdx.x;
    if (e >= NEDGE) return;
    int d = dst[e];
    int pos = atomicAdd(&g_cur[d], 1);
    g_pay[pos] = make_uint2((unsigned)src[e] | ((unsigned)et[e] << 17),
                            __float_as_uint(enorm[e]));
}

// ---------------------------------------------------------------------------
// Aggregation: 2 nodes/warp, 16 lanes/node, uint4 gathers, HADD2/HFMA2
// fp16 accumulate in 8-edge chunks, fp32 flush between chunks.
// ---------------------------------------------------------------------------
__device__ __forceinline__ void agg_edge(uint2 p, int sub, const uint4* H,
                                         const uint4* R, __half2 c[4]) {
    int s = p.x & 0x1FFFF;
    int tt = p.x >> 17;
    __half2 w2 = __float2half2_rn(__uint_as_float(p.y));
    uint4 hv = H[(size_t)s * 16 + sub];
    uint4 rv = R[(size_t)tt * 16 + sub];
    c[0] = __hfma2(__hadd2(u2h(hv.x), u2h(rv.x)), w2, c[0]);
    c[1] = __hfma2(__hadd2(u2h(hv.y), u2h(rv.y)), w2, c[1]);
    c[2] = __hfma2(__hadd2(u2h(hv.z), u2h(rv.z)), w2, c[2]);
    c[3] = __hfma2(__hadd2(u2h(hv.w), u2h(rv.w)), w2, c[3]);
}

__global__ void k_agg() {
    int w = (blockIdx.x * blockDim.x + threadIdx.x) >> 5;
    int lane = threadIdx.x & 31;
    int node = 2 * w + (lane >> 4);
    int sub = lane & 15;
    if (node >= NENT) return;
    int cnt = g_cnt[node];
    int off = g_off[node];
    const uint4* H = (const uint4*)g_hh;
    const uint4* R = (const uint4*)g_relh;
    float2 f[4];
#pragma unroll
    for (int q = 0; q < 4; q++) f[q] = make_float2(0.f, 0.f);

    int nch = cnt >> 3;
    for (int ch = 0; ch < nch; ch++) {
        __half2 c[4];
#pragma unroll
        for (int q = 0; q < 4; q++) c[q] = __float2half2_rn(0.f);
        int base = off + ch * 8;
#pragma unroll
        for (int u = 0; u < 8; u++) {
            uint2 p = g_pay[base + u];
            agg_edge(p, sub, H, R, c);
        }
#pragma unroll
        for (int q = 0; q < 4; q++) {
            float2 d = __half22float2(c[q]);
            f[q].x += d.x; f[q].y += d.y;
        }
    }
    // tail
    {
        __half2 c[4];
#pragma unroll
        for (int q = 0; q < 4; q++) c[q] = __float2half2_rn(0.f);
        for (int i = off + (nch << 3); i < off + cnt; i++) {
            uint2 p = g_pay[i];
            agg_edge(p, sub, H, R, c);
        }
#pragma unroll
        for (int q = 0; q < 4; q++) {
            float2 d = __half22float2(c[q]);
            f[q].x += d.x; f[q].y += d.y;
        }
    }

    // frag store: cols 8*sub..8*sub+7
    int t = node >> 4, lr = node & 15;
    int g = lr & 7, rh = lr >> 3;
    size_t base2 = ((size_t)t * 8 + (sub >> 1)) * 32;
    int j = rh + 2 * (sub & 1);
#pragma unroll
    for (int p = 0; p < 4; p++)
        g_pre_frag[(base2 + g * 4 + p) * 4 + j] = packh2(f[p].x, f[p].y);
}

// ---------------------------------------------------------------------------
// fp16 mma m16n8k16, fp32 accumulate
// ---------------------------------------------------------------------------
__device__ __forceinline__ void mma_f16(float c[4], uint4 a, unsigned b0, unsigned b1) {
    asm volatile(
        "mma.sync.aligned.m16n8k16.row.col.f32.f16.f16.f32 "
        "{%0,%1,%2,%3}, {%4,%5,%6,%7}, {%8,%9}, {%0,%1,%2,%3};"
        : "+f"(c[0]), "+f"(c[1]), "+f"(c[2]), "+f"(c[3])
        : "r"(a.x), "r"(a.y), "r"(a.z), "r"(a.w), "r"(b0), "r"(b1));
}

// ---------------------------------------------------------------------------
// GEMM1: h_cur = rrelu( [pre|h] @ [Wn;Ws] ), fp16 mma. Also re-zeroes g_cnt.
// ---------------------------------------------------------------------------
__global__ void __launch_bounds__(512, 1)
k_gemm1(const float* __restrict__ Wn, const float* __restrict__ Ws) {
    for (int i = blockIdx.x * 512 + threadIdx.x; i < NENT; i += gridDim.x * 512)
        g_cnt[i] = 0;

    extern __shared__ uint2 sW2[];  // 64 rows x PITCH2 uint2
    for (int i = threadIdx.x; i < 64 * 128; i += blockDim.x) {
        int kq = i >> 7, c = i & 127;
        int kk2 = kq >> 2, tig = kq & 3;
        int r0 = 16 * kk2 + 2 * tig;
        int r1 = r0 + 8;
        float a0 = (r0 < 128) ? Wn[r0 * 128 + c] : Ws[(r0 - 128) * 128 + c];
        float a1 = (r0 + 1 < 128) ? Wn[(r0 + 1) * 128 + c] : Ws[(r0 - 127) * 128 + c];
        float b0 = (r1 < 128) ? Wn[r1 * 128 + c] : Ws[(r1 - 128) * 128 + c];
        float b1 = (r1 + 1 < 128) ? Wn[(r1 + 1) * 128 + c] : Ws[(r1 - 127) * 128 + c];
        sW2[kq * PITCH2 + c] = make_uint2(packh2(a0, a1), packh2(b0, b1));
    }
    __syncthreads();

    const int lane = threadIdx.x & 31;
    const int warp = threadIdx.x >> 5;
    const int g = lane >> 2, tig = lane & 3;
    const float SL = 0.22916666666666666f;
    const uint4* preF = (const uint4*)g_pre_frag;
    const uint4* hF = (const uint4*)g_h_frag;

    for (int tile = blockIdx.x * 16 + warp; tile < NTILE; tile += gridDim.x * 16) {
        int n0 = tile * 16;
        float acc[16][4];
#pragma unroll
        for (int nt = 0; nt < 16; nt++) {
            acc[nt][0] = 0.f; acc[nt][1] = 0.f; acc[nt][2] = 0.f; acc[nt][3] = 0.f;
        }

        for (int kk2 = 0; kk2 < 16; kk2++) {
            const uint4* buf = (kk2 < 8) ? preF : hF;
            int ks = kk2 & 7;
            uint4 af = buf[((size_t)tile * 8 + ks) * 32 + lane];
            const uint2* bp = sW2 + (kk2 * 4 + tig) * PITCH2 + g;
#pragma unroll
            for (int nt = 0; nt < 16; nt++) {
                uint2 bb = bp[nt * 8];
                mma_f16(acc[nt], af, bb.x, bb.y);
            }
        }

        float2* out = (float2*)g_hcur;
#pragma unroll
        for (int nt = 0; nt < 16; nt++) {
            float v0 = acc[nt][0], v1 = acc[nt][1], v2 = acc[nt][2], v3 = acc[nt][3];
            v0 = v0 >= 0.f ? v0 : SL * v0;
            v1 = v1 >= 0.f ? v1 : SL * v1;
            v2 = v2 >= 0.f ? v2 : SL * v2;
            v3 = v3 >= 0.f ? v3 : SL * v3;
            out[(size_t)(n0 + g) * 64 + nt * 4 + tig] = make_float2(v0, v1);
            out[(size_t)(n0 + 8 + g) * 64 + nt * 4 + tig] = make_float2(v2, v3);
            size_t base = ((size_t)tile * 8 + (nt >> 1)) * 32 + g * 4 + tig;
            g_hcur_frag[base * 4 + 2 * (nt & 1)]     = packh2(v0, v1);
            g_hcur_frag[base * 4 + 1 + 2 * (nt & 1)] = packh2(v2, v3);
        }
    }
}

// ---------------------------------------------------------------------------
// GEMM2 + gate: gate = sigmoid(h_cur @ Wg + b); out = gate*h_cur + (1-gate)*his
// ---------------------------------------------------------------------------
__global__ void __launch_bounds__(512, 1)
k_gemm2(const float* __restrict__ Wg, const float* __restrict__ bias,
        const float* __restrict__ his, float* __restrict__ outp) {
    extern __shared__ uint2 sW2[];  // 32 rows x PITCH2 uint2
    for (int i = threadIdx.x; i < 32 * 128; i += blockDim.x) {
        int kq = i >> 7, c = i & 127;
        int kk2 = kq >> 2, tig = kq & 3;
        int r0 = 16 * kk2 + 2 * tig;
        int r1 = r0 + 8;
        sW2[kq * PITCH2 + c] = make_uint2(
            packh2(Wg[r0 * 128 + c], Wg[(r0 + 1) * 128 + c]),
            packh2(Wg[r1 * 128 + c], Wg[(r1 + 1) * 128 + c]));
    }
    __syncthreads();

    const int lane = threadIdx.x & 31;
    const int warp = threadIdx.x >> 5;
    const int g = lane >> 2, tig = lane & 3;
    const uint4* hcF = (const uint4*)g_hcur_frag;

    float2 bs[16];
#pragma unroll
    for (int nt = 0; nt < 16; nt++)
        bs[nt] = ((const float2*)bias)[nt * 4 + tig];

    for (int tile = blockIdx.x * 16 + warp; tile < NTILE; tile += gridDim.x * 16) {
        int n0 = tile * 16;
        float acc[16][4];
#pragma unroll
        for (int nt = 0; nt < 16; nt++) {
            acc[nt][0] = 0.f; acc[nt][1] = 0.f; acc[nt][2] = 0.f; acc[nt][3] = 0.f;
        }

        for (int kk2 = 0; kk2 < 8; kk2++) {
            uint4 af = hcF[((size_t)tile * 8 + kk2) * 32 + lane];
            const uint2* bp = sW2 + (kk2 * 4 + tig) * PITCH2 + g;
#pragma unroll
            for (int nt = 0; nt < 16; nt++) {
                uint2 bb = bp[nt * 8];
                mma_f16(acc[nt], af, bb.x, bb.y);
            }
        }

        const float2* hc2 = (const float2*)g_hcur;
        const float2* hs2 = (const float2*)his;
        float2* o2 = (float2*)outp;
#pragma unroll
        for (int nt = 0; nt < 16; nt++) {
            {
                size_t idx = (size_t)(n0 + g) * 64 + nt * 4 + tig;
                float2 hc = hc2[idx];
                float2 hs = hs2[idx];
                float gx = 1.0f / (1.0f + expf(-(acc[nt][0] + bs[nt].x)));
                float gy = 1.0f / (1.0f + expf(-(acc[nt][1] + bs[nt].y)));
                float2 o;
                o.x = fmaf(gx, hc.x - hs.x, hs.x);
                o.y = fmaf(gy, hc.y - hs.y, hs.y);
                o2[idx] = o;
            }
            {
                size_t idx = (size_t)(n0 + 8 + g) * 64 + nt * 4 + tig;
                float2 hc = hc2[idx];
                float2 hs = hs2[idx];
                float gx = 1.0f / (1.0f + expf(-(acc[nt][2] + bs[nt].x)));
                float gy = 1.0f / (1.0f + expf(-(acc[nt][3] + bs[nt].y)));
                float2 o;
                o.x = fmaf(gx, hc.x - hs.x, hs.x);
                o.y = fmaf(gy, hc.y - hs.y, hs.y);
                o2[idx] = o;
            }
        }
    }
}

// ---------------------------------------------------------------------------
// Launch: 7 kernels
// ---------------------------------------------------------------------------
extern "C" void kernel_launch(void* const* d_in, const int* in_sizes, int n_in,
                              void* d_out, int out_size) {
    const float4* ent  = (const float4*)d_in[0];
    const float4* rel  = (const float4*)d_in[1];
    const float*  his  = (const float*)d_in[2];
    const float*  Wn   = (const float*)d_in[3];
    const float*  Ws   = (const float*)d_in[4];
    const float*  Wg   = (const float*)d_in[5];
    const float*  bias = (const float*)d_in[6];
    const float*  enorm = (const float*)d_in[7];
    const int*    src  = (const int*)d_in[8];
    const int*    dst  = (const int*)d_in[9];
    const int*    et   = (const int*)d_in[10];
    float* out = (float*)d_out;

    k_fused<<<NB_NORM + NB_REL + NB_HIST, 256>>>(ent, rel, dst);
    k_scan1<<<SCAN_B, 512>>>();
    k_scan2<<<SCAN_B, 512>>>();
    k_scatter<<<(NEDGE + 511) / 512, 512>>>(enorm, src, dst, et);
    k_agg<<<3125, 512>>>();
    {
        int smem = 64 * PITCH2 * 8;
        cudaFuncSetAttribute(k_gemm1, cudaFuncAttributeMaxDynamicSharedMemorySize, smem);
        k_gemm1<<<148, 512, smem>>>(Wn, Ws);
    }
    {
        int smem = 32 * PITCH2 * 8;
        cudaFuncSetAttribute(k_gemm2, cudaFuncAttributeMaxDynamicSharedMemorySize, smem);
        k_gemm2<<<148, 512, smem>>>(Wg, bias, his, out);
    }
}